// round 10
// baseline (speedup 1.0000x reference)
#include <cuda_runtime.h>
#include <cuda_fp16.h>
#include <cstdint>

#define EPS 1e-6f
// B=8, S=4096, IN=1024, HD=1024, OUT=1024, M=32768

// ---------------- scratch (allocation-free device globals) ----------------
__device__ __half g_xh [33554432];  // fp16 x            [32768,1024] (64MB)
__device__ __half g_wkv[2097152];   // concat [2048,1024]: blk j = [Wk 64 | Wv 64] cols
__device__ __half g_wqT[1048576];   // [N,K] transposed fp16
__device__ __half g_woT[1048576];
__device__ __half g_att[33554432];  // attn scratch fp16 (64MB)
__device__ float  g_KV[8192];       // [B, H*D]
__device__ float  g_KS[8192];

// ---------------- helpers ----------------
__device__ __forceinline__ uint32_t sptr(const void* p) {
    return (uint32_t)__cvta_generic_to_shared(p);
}
__device__ __forceinline__ void cpa16(uint32_t d, const void* s) {
    asm volatile("cp.async.cg.shared.global [%0], [%1], 16;\n" :: "r"(d), "l"(s));
}
__device__ __forceinline__ void cp_commit() { asm volatile("cp.async.commit_group;\n"); }
template<int N> __device__ __forceinline__ void cp_wait() {
    asm volatile("cp.async.wait_group %0;\n" :: "n"(N));
}
__device__ __forceinline__ void ldsm4(uint32_t& r0, uint32_t& r1, uint32_t& r2, uint32_t& r3,
                                      uint32_t a) {
    asm volatile("ldmatrix.sync.aligned.m8n8.x4.shared.b16 {%0,%1,%2,%3}, [%4];"
                 : "=r"(r0), "=r"(r1), "=r"(r2), "=r"(r3) : "r"(a));
}
__device__ __forceinline__ void mma16(float* c, const uint32_t* a, const uint32_t* b) {
    asm volatile(
        "mma.sync.aligned.m16n8k16.row.col.f32.f16.f16.f32 "
        "{%0,%1,%2,%3}, {%4,%5,%6,%7}, {%8,%9}, {%0,%1,%2,%3};"
        : "+f"(c[0]), "+f"(c[1]), "+f"(c[2]), "+f"(c[3])
        : "r"(a[0]), "r"(a[1]), "r"(a[2]), "r"(a[3]), "r"(b[0]), "r"(b[1]));
}
__device__ __forceinline__ float fmap(float x) {   // elu(x)+1
    return x > 0.f ? x + 1.f : __expf(x);
}
__device__ __forceinline__ float gelu_t(float x) { // tanh-approx gelu
    float x3 = x * x * x;
    float t  = tanhf(0.7978845608028654f * (x + 0.044715f * x3));
    return 0.5f * x * (1.f + t);
}

// ---------------- prep kernels ----------------
__global__ void k_tohalf(const float2* __restrict__ src, __half2* __restrict__ dst, int n2) {
    int i = blockIdx.x * blockDim.x + threadIdx.x;
    if (i < n2) { float2 v = src[i]; dst[i] = __float22half2_rn(v); }
}
// transpose 1024x1024 [K][N] -> [N][K] fp16; z=0 -> wq, z=1 -> wo
__global__ void k_wt(const float* __restrict__ s0, __half* __restrict__ d0,
                     const float* __restrict__ s1, __half* __restrict__ d1)
{
    __shared__ float t[32][33];
    const float* src = blockIdx.z ? s1 : s0;
    __half* dst      = blockIdx.z ? d1 : d0;
    int bx = blockIdx.x << 5, by = blockIdx.y << 5;
    int tx = threadIdx.x, ty = threadIdx.y;   // 32 x 8
#pragma unroll
    for (int i = 0; i < 4; i++)
        t[ty + i * 8][tx] = src[(size_t)(by + ty + i * 8) * 1024 + bx + tx];
    __syncthreads();
#pragma unroll
    for (int i = 0; i < 4; i++)
        dst[(size_t)(bx + ty + i * 8) * 1024 + by + tx] = __float2half_rn(t[tx][ty + i * 8]);
}
// build concat W_kv [2048,1024]: concat row 128*(n>>6)+(n&63)+64*isV = W[:,n]^T
__global__ void k_wkv(const float* __restrict__ wk, const float* __restrict__ wv,
                      __half* __restrict__ dst)
{
    __shared__ float t[32][33];
    const float* src = blockIdx.z ? wv : wk;
    int bx = blockIdx.x << 5, by = blockIdx.y << 5;  // bx: n, by: k
    int tx = threadIdx.x, ty = threadIdx.y;
#pragma unroll
    for (int i = 0; i < 4; i++)
        t[ty + i * 8][tx] = src[(size_t)(by + ty + i * 8) * 1024 + bx + tx];
    __syncthreads();
    int base = 128 * (bx >> 6) + (bx & 63) + (blockIdx.z ? 64 : 0);
#pragma unroll
    for (int i = 0; i < 4; i++)
        dst[(size_t)(base + ty + i * 8) * 1024 + by + tx] = __float2half_rn(t[tx][ty + i * 8]);
}
__global__ void k_zero(float* a, float* b, int n) {
    int i = blockIdx.x * blockDim.x + threadIdx.x;
    if (i < n) { a[i] = 0.f; b[i] = 0.f; }
}

// swizzled smem byte address of 16B chunk (r row of 128B, c chunk 0..7)
#define SWC(base, r, c) ((base) + (r) * 128 + (((c) ^ ((r) & 7)) << 4))

// ---------------- common mainloop ----------------
// BM=128, BN=256, BK=64, 256 thr, 8 warps 2(m)x4(n), warp tile 64x64
// 4 stages x (A 16K + B 32K) = 192K smem, 1 CTA/SM
// fragments double-buffered across ks so MMA bursts never wait on LDSM
#define LOAD_FRAGS(buf, ks)                                                             \
    {                                                                                   \
        _Pragma("unroll") for (int mi = 0; mi < 4; mi++) {                              \
            const int r = rA0 + mi * 16;                                                \
            ldsm4(af[buf][mi][0], af[buf][mi][1], af[buf][mi][2], af[buf][mi][3],       \
                  sa + r * 128 + (((2 * (ks) + selA) ^ (r & 7)) << 4));                 \
        }                                                                               \
        _Pragma("unroll") for (int p = 0; p < 4; p++) {                                 \
            const int c = cB0 + p * 16;                                                 \
            ldsm4(bf[buf][2 * p][0], bf[buf][2 * p][1],                                 \
                  bf[buf][2 * p + 1][0], bf[buf][2 * p + 1][1],                         \
                  sb + c * 128 + (((2 * (ks) + selB) ^ (c & 7)) << 4));                 \
        }                                                                               \
    }

#define GEMM_MAIN(WT)                                                                   \
    extern __shared__ char sm[];                                                        \
    const uint32_t smb = sptr(sm);                                                      \
    const int tid = threadIdx.x, lane = tid & 31, wid = tid >> 5;                       \
    const int wm = wid >> 2, wn = wid & 3;                                              \
    const int rowBase = blockIdx.y << 7;                                                \
    const int colBase = blockIdx.x << 8;                                                \
    float acc[4][8][4];                                                                 \
    _Pragma("unroll") for (int i = 0; i < 4; i++)                                       \
    _Pragma("unroll") for (int j = 0; j < 8; j++)                                       \
    _Pragma("unroll") for (int c = 0; c < 4; c++) acc[i][j][c] = 0.f;                   \
    auto load_chunk = [&](int kt, int s) {                                              \
        const uint32_t sA = smb + s * 49152;                                            \
        const uint32_t sB = sA + 16384;                                                 \
        const __half* gA = A  + (size_t)rowBase * 1024 + kt * 64;                       \
        const __half* gB = WT + (size_t)colBase * 1024 + kt * 64;                       \
        _Pragma("unroll") for (int l = 0; l < 4; l++) {                                 \
            int e = l * 256 + tid, r = e >> 3, c = e & 7;                               \
            cpa16(SWC(sA, r, c), gA + (size_t)r * 1024 + c * 8);                        \
        }                                                                               \
        _Pragma("unroll") for (int l = 0; l < 8; l++) {                                 \
            int e = l * 256 + tid, r = e >> 3, c = e & 7;                               \
            cpa16(SWC(sB, r, c), gB + (size_t)r * 1024 + c * 8);                        \
        }                                                                               \
        cp_commit();                                                                    \
    };                                                                                  \
    load_chunk(0, 0);                                                                   \
    load_chunk(1, 1);                                                                   \
    load_chunk(2, 2);                                                                   \
    const int rA0 = wm * 64 + (lane & 15);                                              \
    const int selA = lane >> 4;                                                         \
    const int cB0 = wn * 64 + (lane & 7) + ((lane >> 4) << 3);                          \
    const int selB = (lane >> 3) & 1;                                                   \
    uint32_t af[2][4][4], bf[2][8][2];                                                  \
    for (int kt = 0; kt < 16; kt++) {                                                   \
        if (kt < 14) cp_wait<2>(); else if (kt < 15) cp_wait<1>(); else cp_wait<0>();   \
        __syncthreads();                                                                \
        if (kt < 13) load_chunk(kt + 3, (kt + 3) & 3);                                  \
        const uint32_t sa = smb + (kt & 3) * 49152;                                     \
        const uint32_t sb = sa + 16384;                                                 \
        LOAD_FRAGS(0, 0)                                                                \
        _Pragma("unroll") for (int ks = 0; ks < 4; ks++) {                              \
            const int cur = ks & 1;                                                     \
            if (ks < 3) LOAD_FRAGS(cur ^ 1, ks + 1)                                     \
            _Pragma("unroll") for (int mi = 0; mi < 4; mi++)                            \
            _Pragma("unroll") for (int ni = 0; ni < 8; ni++)                            \
                mma16(acc[mi][ni], af[cur][mi], bf[cur][ni]);                           \
        }                                                                               \
    }

// ---------------- Kernel 1: fused K/V GEMM (concat weights) + reduction ----------------
// grid (8, 256): CTA covers concat blocks 2bx, 2bx+1 -> dims 128bx..128bx+127
// warp wn: 0 = K(dl 0..63), 1 = V(dl 0..63), 2 = K(dl 64..127), 3 = V(dl 64..127)
__global__ void __launch_bounds__(256, 1) k_kv(
    const __half* __restrict__ A, const __half* __restrict__ Wkv,
    const float* __restrict__ BK, const float* __restrict__ BV,
    float* __restrict__ KV, float* __restrict__ KS)
{
    GEMM_MAIN(Wkv)

    // V-warps park V accs in smem, K-warps pair + reduce
    float* smE = (float*)sm;   // [128][132] fp32
    __syncthreads();           // mainloop smem reads complete before overwrite
    if (wn & 1) {              // V warps
        const int dbase = (wn >> 1) << 6;
#pragma unroll
        for (int mi = 0; mi < 4; mi++)
#pragma unroll
            for (int ni = 0; ni < 8; ni++) {
                const int dl = dbase + ni * 8 + 2 * (lane & 3);
#pragma unroll
                for (int h = 0; h < 2; h++) {
                    const int row = wm * 64 + mi * 16 + (lane >> 2) + 8 * h;
                    *(float2*)&smE[row * 132 + dl] =
                        make_float2(acc[mi][ni][2 * h], acc[mi][ni][2 * h + 1]);
                }
            }
    }
    __syncthreads();
    if (!(wn & 1)) {           // K warps: fmap, pair with V, reduce over rows
        const int b = rowBase >> 12;
        const int dHalf = (wn >> 1) << 6;
        const int dims0 = (colBase >> 1) + dHalf;
#pragma unroll
        for (int ni = 0; ni < 8; ni++) {
#pragma unroll
            for (int c = 0; c < 2; c++) {
                const int dl = dHalf + ni * 8 + 2 * (lane & 3) + c;
                const int d  = dims0 + ni * 8 + 2 * (lane & 3) + c;
                const float bkc = BK[d], bvc = BV[d];
                float skv = 0.f, sk = 0.f;
#pragma unroll
                for (int mi = 0; mi < 4; mi++) {
#pragma unroll
                    for (int h = 0; h < 2; h++) {
                        const int row = wm * 64 + mi * 16 + (lane >> 2) + 8 * h;
                        float Kv = fmap(acc[mi][ni][2 * h + c] + bkc);
                        float Vv = smE[row * 132 + dl] + bvc;
                        skv += Kv * Vv;
                        sk  += Kv;
                    }
                }
#pragma unroll
                for (int off = 16; off >= 4; off >>= 1) {
                    skv += __shfl_xor_sync(0xffffffffu, skv, off);
                    sk  += __shfl_xor_sync(0xffffffffu, sk,  off);
                }
                if (lane < 4) {
                    const int dd = dims0 + ni * 8 + 2 * lane + c;
                    atomicAdd(&KV[b * 1024 + dd], skv);
                    atomicAdd(&KS[b * 1024 + dd], sk);
                }
            }
        }
    }
}

// ---------------- Kernel 2: Q projection + attn epilogue (fp16 out) ----------------
__global__ void __launch_bounds__(256, 1) k_q_attn(
    const __half* __restrict__ A, const __half* __restrict__ WT,
    const float* __restrict__ BQ, const float* __restrict__ KV,
    const float* __restrict__ KS, __half* __restrict__ ATT)
{
    GEMM_MAIN(WT)
    const int b = rowBase >> 12;
    const int g = lane >> 2;
#pragma unroll
    for (int mi = 0; mi < 4; mi++) {
        const int r0 = rowBase + wm * 64 + mi * 16 + g;
#pragma unroll
        for (int ni = 0; ni < 8; ni++) {
            const int c0 = colBase + wn * 64 + ni * 8 + 2 * (lane & 3);
            const float kv0 = KV[b * 1024 + c0], kv1 = KV[b * 1024 + c0 + 1];
            const float ks0 = KS[b * 1024 + c0], ks1 = KS[b * 1024 + c0 + 1];
            const float bq0 = BQ[c0], bq1 = BQ[c0 + 1];
#pragma unroll
            for (int h = 0; h < 2; h++) {
                const int r = r0 + 8 * h;
                float Q0 = fmap(acc[mi][ni][2 * h + 0] + bq0);
                float Q1 = fmap(acc[mi][ni][2 * h + 1] + bq1);
                float a0 = Q0 * kv0 / (Q0 * ks0 + EPS);
                float a1 = Q1 * kv1 / (Q1 * ks1 + EPS);
                *(__half2*)(&ATT[(size_t)r * 1024 + c0]) = __floats2half2_rn(a0, a1);
            }
        }
    }
}

// ---------------- Kernel 3: output projection + gelu (fp32 out) ----------------
__global__ void __launch_bounds__(256, 1) k_out(
    const __half* __restrict__ A, const __half* __restrict__ WT,
    const float* __restrict__ BO, float* __restrict__ OUT)
{
    GEMM_MAIN(WT)
    const int g = lane >> 2;
#pragma unroll
    for (int mi = 0; mi < 4; mi++) {
        const int r0 = rowBase + wm * 64 + mi * 16 + g;
#pragma unroll
        for (int ni = 0; ni < 8; ni++) {
            const int c0 = colBase + wn * 64 + ni * 8 + 2 * (lane & 3);
            const float bo0 = BO[c0], bo1 = BO[c0 + 1];
#pragma unroll
            for (int h = 0; h < 2; h++) {
                const int r = r0 + 8 * h;
                float o0 = gelu_t(acc[mi][ni][2 * h + 0] + bo0);
                float o1 = gelu_t(acc[mi][ni][2 * h + 1] + bo1);
                *(float2*)(&OUT[(size_t)r * 1024 + c0]) = make_float2(o0, o1);
            }
        }
    }
}

// ---------------- host launcher ----------------
extern "C" void kernel_launch(void* const* d_in, const int* in_sizes, int n_in,
                              void* d_out, int out_size)
{
    const float* x  = (const float*)d_in[0];
    const float* wq = (const float*)d_in[1];
    const float* bq = (const float*)d_in[2];
    const float* wk = (const float*)d_in[3];
    const float* bk = (const float*)d_in[4];
    const float* wv = (const float*)d_in[5];
    const float* bv = (const float*)d_in[6];
    const float* wo = (const float*)d_in[7];
    const float* bo = (const float*)d_in[8];
    float* out = (float*)d_out;

    void *p_xh, *p_wkv, *p_wq, *p_wo, *p_att, *p_kv, *p_ks;
    cudaGetSymbolAddress(&p_xh,  g_xh);
    cudaGetSymbolAddress(&p_wkv, g_wkv);
    cudaGetSymbolAddress(&p_wq,  g_wqT);
    cudaGetSymbolAddress(&p_wo,  g_woT);
    cudaGetSymbolAddress(&p_att, g_att);
    cudaGetSymbolAddress(&p_kv,  g_KV);
    cudaGetSymbolAddress(&p_ks,  g_KS);

    const int SMB = 196608;  // 4 stages x 48K; k_kv exchange 128*132*4 = 67.5K fits
    cudaFuncSetAttribute(k_kv,     cudaFuncAttributeMaxDynamicSharedMemorySize, SMB);
    cudaFuncSetAttribute(k_q_attn, cudaFuncAttributeMaxDynamicSharedMemorySize, SMB);
    cudaFuncSetAttribute(k_out,    cudaFuncAttributeMaxDynamicSharedMemorySize, SMB);

    // prep: x -> fp16; weights -> transposed fp16 (+ K/V concat); zero accumulators
    k_tohalf<<<65536, 256>>>((const float2*)x, (__half2*)p_xh, 16777216);
    k_wt<<<dim3(32, 32, 2), dim3(32, 8)>>>(wq, (__half*)p_wq, wo, (__half*)p_wo);
    k_wkv<<<dim3(32, 32, 2), dim3(32, 8)>>>(wk, wv, (__half*)p_wkv);
    k_zero<<<8, 1024>>>((float*)p_kv, (float*)p_ks, 8192);

    // 1) fused K,V projections + KV/Ksum reduction (K,V never hit DRAM)
    k_kv<<<dim3(8, 256), 256, SMB>>>((const __half*)p_xh, (const __half*)p_wkv,
                                     bk, bv, (float*)p_kv, (float*)p_ks);
    // 2) Q projection + linear-attention epilogue -> attn scratch (fp16)
    k_q_attn<<<dim3(4, 256), 256, SMB>>>((const __half*)p_xh, (const __half*)p_wq, bq,
                                         (const float*)p_kv, (const float*)p_ks,
                                         (__half*)p_att);
    // 3) output projection + gelu
    k_out<<<dim3(4, 256), 256, SMB>>>((const __half*)p_att, (const __half*)p_wo, bo, out);
}

// round 11
// speedup vs baseline: 1.1753x; 1.1753x over previous
#include <cuda_runtime.h>
#include <cuda_fp16.h>
#include <cstdint>

#define EPS 1e-6f
// B=8, S=4096, IN=1024, HD=1024, OUT=1024, M=32768

// ---------------- scratch (allocation-free device globals) ----------------
__device__ __half g_xh [33554432];  // fp16 x            [32768,1024] (64MB)
__device__ __half g_wqT[1048576];   // [N,K] transposed fp16
__device__ __half g_wkT[1048576];
__device__ __half g_wvT[1048576];
__device__ __half g_woT[1048576];
__device__ __half g_att[33554432];  // attn scratch fp16 (64MB)
__device__ float  g_KV[8192];       // [B, H*D]
__device__ float  g_KS[8192];

// ---------------- helpers ----------------
__device__ __forceinline__ uint32_t sptr(const void* p) {
    return (uint32_t)__cvta_generic_to_shared(p);
}
__device__ __forceinline__ void cpa16(uint32_t d, const void* s) {
    asm volatile("cp.async.cg.shared.global [%0], [%1], 16;\n" :: "r"(d), "l"(s));
}
__device__ __forceinline__ void cp_commit() { asm volatile("cp.async.commit_group;\n"); }
template<int N> __device__ __forceinline__ void cp_wait() {
    asm volatile("cp.async.wait_group %0;\n" :: "n"(N));
}
__device__ __forceinline__ void ldsm4(uint32_t& r0, uint32_t& r1, uint32_t& r2, uint32_t& r3,
                                      uint32_t a) {
    asm volatile("ldmatrix.sync.aligned.m8n8.x4.shared.b16 {%0,%1,%2,%3}, [%4];"
                 : "=r"(r0), "=r"(r1), "=r"(r2), "=r"(r3) : "r"(a));
}
__device__ __forceinline__ void mma16(float* c, const uint32_t* a, const uint32_t* b) {
    asm volatile(
        "mma.sync.aligned.m16n8k16.row.col.f32.f16.f16.f32 "
        "{%0,%1,%2,%3}, {%4,%5,%6,%7}, {%8,%9}, {%0,%1,%2,%3};"
        : "+f"(c[0]), "+f"(c[1]), "+f"(c[2]), "+f"(c[3])
        : "r"(a[0]), "r"(a[1]), "r"(a[2]), "r"(a[3]), "r"(b[0]), "r"(b[1]));
}
__device__ __forceinline__ float fmap(float x) {   // elu(x)+1
    return x > 0.f ? x + 1.f : __expf(x);
}
__device__ __forceinline__ float gelu_t(float x) { // tanh-approx gelu
    float x3 = x * x * x;
    float t  = tanhf(0.7978845608028654f * (x + 0.044715f * x3));
    return 0.5f * x * (1.f + t);
}

// ---------------- prep kernels ----------------
__global__ void k_tohalf(const float4* __restrict__ src, __half2* __restrict__ dst, int n4) {
    int i = blockIdx.x * blockDim.x + threadIdx.x;
    if (i < n4) {
        float4 v = src[i];
        dst[2 * i]     = __floats2half2_rn(v.x, v.y);
        dst[2 * i + 1] = __floats2half2_rn(v.z, v.w);
    }
}
// transpose 1024x1024 [K][N] -> [N][K], convert to fp16; blockIdx.z picks matrix
__global__ void k_wt(const float* __restrict__ s0, __half* __restrict__ d0,
                     const float* __restrict__ s1, __half* __restrict__ d1,
                     const float* __restrict__ s2, __half* __restrict__ d2,
                     const float* __restrict__ s3, __half* __restrict__ d3)
{
    __shared__ float t[32][33];
    const float* src; __half* dst;
    switch (blockIdx.z) {
        case 0:  src = s0; dst = d0; break;
        case 1:  src = s1; dst = d1; break;
        case 2:  src = s2; dst = d2; break;
        default: src = s3; dst = d3; break;
    }
    int bx = blockIdx.x << 5, by = blockIdx.y << 5;
    int tx = threadIdx.x, ty = threadIdx.y;   // 32 x 8
#pragma unroll
    for (int i = 0; i < 4; i++)
        t[ty + i * 8][tx] = src[(size_t)(by + ty + i * 8) * 1024 + bx + tx];
    __syncthreads();
#pragma unroll
    for (int i = 0; i < 4; i++)
        dst[(size_t)(bx + ty + i * 8) * 1024 + by + tx] = __float2half_rn(t[tx][ty + i * 8]);
}
__global__ void k_zero(float* a, float* b, int n) {
    int i = blockIdx.x * blockDim.x + threadIdx.x;
    if (i < n) { a[i] = 0.f; b[i] = 0.f; }
}

// swizzled smem byte address of 16B chunk (r row of 128B, c chunk 0..7)
#define SWC(base, r, c) ((base) + (r) * 128 + (((c) ^ ((r) & 7)) << 4))

// ---------------- Kernel 1: K/V dual-GEMM + KV/Ksum reduction ----------------
// BM=128, BN=64, BK=64, 256 thr, warps 4(m)x2(n), warp tile 32x32
// smem/stage: A 16K + Bk 8K + Bv 8K = 32K; 3 stages = 96K; 2 CTA/SM
__global__ void __launch_bounds__(256) k_kv(
    const __half* __restrict__ X, const __half* __restrict__ WkT, const __half* __restrict__ WvT,
    const float* __restrict__ BK, const float* __restrict__ BV,
    float* __restrict__ KV, float* __restrict__ KS)
{
    extern __shared__ char sm[];
    const uint32_t smb = sptr(sm);
    const int tid = threadIdx.x, lane = tid & 31, wid = tid >> 5;
    const int wm = wid >> 1, wn = wid & 1;
    const int rowBase = blockIdx.y << 7;
    const int colBase = blockIdx.x << 6;

    float accK[2][4][4], accV[2][4][4];
#pragma unroll
    for (int i = 0; i < 2; i++)
#pragma unroll
        for (int j = 0; j < 4; j++)
#pragma unroll
            for (int c = 0; c < 4; c++) { accK[i][j][c] = 0.f; accV[i][j][c] = 0.f; }

    auto load_chunk = [&](int kt, int s) {
        const uint32_t sa  = smb + s * 32768;
        const uint32_t sbk = sa + 16384;
        const uint32_t sbv = sbk + 8192;
        const __half* gA = X   + (size_t)rowBase * 1024 + kt * 64;
        const __half* gK = WkT + (size_t)colBase * 1024 + kt * 64;
        const __half* gV = WvT + (size_t)colBase * 1024 + kt * 64;
#pragma unroll
        for (int l = 0; l < 4; l++) {
            int e = l * 256 + tid, r = e >> 3, c = e & 7;
            cpa16(SWC(sa, r, c), gA + (size_t)r * 1024 + c * 8);
        }
#pragma unroll
        for (int l = 0; l < 2; l++) {
            int e = l * 256 + tid, r = e >> 3, c = e & 7;
            cpa16(SWC(sbk, r, c), gK + (size_t)r * 1024 + c * 8);
            cpa16(SWC(sbv, r, c), gV + (size_t)r * 1024 + c * 8);
        }
        cp_commit();
    };

    load_chunk(0, 0);
    load_chunk(1, 1);

    // ldmatrix lane roles
    const int rA0 = wm * 32 + (lane & 15);        // + mi*16
    const int selA = lane >> 4;                   // chunk +0/+1
    const int cB0 = wn * 32 + (lane & 7) + ((lane >> 4) << 3);  // + pair*16
    const int selB = (lane >> 3) & 1;

    for (int kt = 0; kt < 16; kt++) {
        if (kt < 15) cp_wait<1>(); else cp_wait<0>();
        __syncthreads();
        const int s = kt % 3;
        const uint32_t sa  = smb + s * 32768;
        const uint32_t sbk = sa + 16384;
        const uint32_t sbv = sbk + 8192;
#pragma unroll
        for (int ks = 0; ks < 4; ks++) {
            uint32_t af[2][4], bk2[4][2], bv2[4][2];
#pragma unroll
            for (int mi = 0; mi < 2; mi++) {
                const int r = rA0 + mi * 16;
                ldsm4(af[mi][0], af[mi][1], af[mi][2], af[mi][3],
                      sa + r * 128 + (((2 * ks + selA) ^ (r & 7)) << 4));
            }
#pragma unroll
            for (int p = 0; p < 2; p++) {
                const int c = cB0 + p * 16;
                const uint32_t off = c * 128 + (((2 * ks + selB) ^ (c & 7)) << 4);
                ldsm4(bk2[2 * p][0], bk2[2 * p][1], bk2[2 * p + 1][0], bk2[2 * p + 1][1],
                      sbk + off);
                ldsm4(bv2[2 * p][0], bv2[2 * p][1], bv2[2 * p + 1][0], bv2[2 * p + 1][1],
                      sbv + off);
            }
            // overlap next-chunk cp.async issue with ks=0 LDSM latency
            if (ks == 0 && kt < 14) load_chunk(kt + 2, (kt + 2) % 3);
#pragma unroll
            for (int mi = 0; mi < 2; mi++)
#pragma unroll
                for (int ni = 0; ni < 4; ni++) {
                    mma16(accK[mi][ni], af[mi], bk2[ni]);
                    mma16(accV[mi][ni], af[mi], bv2[ni]);
                }
        }
    }

    // epilogue: K = elu+1, reduce K*v and K over the 128 s-rows of this block
    const int b = rowBase >> 12;
#pragma unroll
    for (int ni = 0; ni < 4; ni++) {
#pragma unroll
        for (int c = 0; c < 2; c++) {
            const int colg = colBase + wn * 32 + ni * 8 + 2 * (lane & 3) + c;
            const float bkc = BK[colg], bvc = BV[colg];
            float skv = 0.f, sk = 0.f;
#pragma unroll
            for (int mi = 0; mi < 2; mi++) {
                float kA = accK[mi][ni][c]     + bkc;
                float kB = accK[mi][ni][c + 2] + bkc;
                float vA = accV[mi][ni][c]     + bvc;
                float vB = accV[mi][ni][c + 2] + bvc;
                float KA = fmap(kA), KB = fmap(kB);
                skv += KA * vA + KB * vB;
                sk  += KA + KB;
            }
#pragma unroll
            for (int off = 16; off >= 4; off >>= 1) {
                skv += __shfl_xor_sync(0xffffffffu, skv, off);
                sk  += __shfl_xor_sync(0xffffffffu, sk,  off);
            }
            if (lane < 4) {
                atomicAdd(&KV[b * 1024 + colg], skv);
                atomicAdd(&KS[b * 1024 + colg], sk);
            }
        }
    }
}

// ---------------- Kernels 2/3 common mainloop ----------------
// BM=128, BN=128, BK=64, 256 thr, warps 2(m)x4(n), warp tile 64x32
// smem/stage: A 16K + B 16K = 32K; 3 stages = 96K; 2 CTA/SM
#define GEMM_MAIN(WT)                                                                   \
    extern __shared__ char sm[];                                                        \
    const uint32_t smb = sptr(sm);                                                      \
    const int tid = threadIdx.x, lane = tid & 31, wid = tid >> 5;                       \
    const int wm = wid >> 2, wn = wid & 3;                                              \
    const int rowBase = blockIdx.y << 7;                                                \
    const int colBase = blockIdx.x << 7;                                                \
    float acc[4][4][4];                                                                 \
    _Pragma("unroll") for (int i = 0; i < 4; i++)                                       \
    _Pragma("unroll") for (int j = 0; j < 4; j++)                                       \
    _Pragma("unroll") for (int c = 0; c < 4; c++) acc[i][j][c] = 0.f;                   \
    auto load_chunk = [&](int kt, int s) {                                              \
        const uint32_t sa = smb + s * 32768;                                            \
        const uint32_t sb = sa + 16384;                                                 \
        const __half* gA = A  + (size_t)rowBase * 1024 + kt * 64;                       \
        const __half* gB = WT + (size_t)colBase * 1024 + kt * 64;                       \
        _Pragma("unroll") for (int l = 0; l < 4; l++) {                                 \
            int e = l * 256 + tid, r = e >> 3, c = e & 7;                               \
            cpa16(SWC(sa, r, c), gA + (size_t)r * 1024 + c * 8);                        \
            cpa16(SWC(sb, r, c), gB + (size_t)r * 1024 + c * 8);                        \
        }                                                                               \
        cp_commit();                                                                    \
    };                                                                                  \
    load_chunk(0, 0);                                                                   \
    load_chunk(1, 1);                                                                   \
    const int rA0 = wm * 64 + (lane & 15);                                              \
    const int selA = lane >> 4;                                                         \
    const int cB0 = wn * 32 + (lane & 7) + ((lane >> 4) << 3);                          \
    const int selB = (lane >> 3) & 1;                                                   \
    for (int kt = 0; kt < 16; kt++) {                                                   \
        if (kt < 15) cp_wait<1>(); else cp_wait<0>();                                   \
        __syncthreads();                                                                \
        const int s = kt % 3;                                                           \
        const uint32_t sa = smb + s * 32768;                                            \
        const uint32_t sb = sa + 16384;                                                 \
        _Pragma("unroll") for (int ks = 0; ks < 4; ks++) {                              \
            uint32_t af[4][4], bf[4][2];                                                \
            _Pragma("unroll") for (int mi = 0; mi < 4; mi++) {                          \
                const int r = rA0 + mi * 16;                                            \
                ldsm4(af[mi][0], af[mi][1], af[mi][2], af[mi][3],                       \
                      sa + r * 128 + (((2 * ks + selA) ^ (r & 7)) << 4));               \
            }                                                                           \
            _Pragma("unroll") for (int p = 0; p < 2; p++) {                             \
                const int c = cB0 + p * 16;                                             \
                ldsm4(bf[2 * p][0], bf[2 * p][1], bf[2 * p + 1][0], bf[2 * p + 1][1],   \
                      sb + c * 128 + (((2 * ks + selB) ^ (c & 7)) << 4));               \
            }                                                                           \
            if (ks == 0 && kt < 14) load_chunk(kt + 2, (kt + 2) % 3);                   \
            _Pragma("unroll") for (int mi = 0; mi < 4; mi++)                            \
            _Pragma("unroll") for (int ni = 0; ni < 4; ni++)                            \
                mma16(acc[mi][ni], af[mi], bf[ni]);                                     \
        }                                                                               \
    }

// ---------------- Kernel 2: Q projection + attn epilogue (fp16 out) ----------------
__global__ void __launch_bounds__(256) k_q_attn(
    const __half* __restrict__ A, const __half* __restrict__ WT,
    const float* __restrict__ BQ, const float* __restrict__ KV,
    const float* __restrict__ KS, __half* __restrict__ ATT)
{
    GEMM_MAIN(WT)
    const int b = rowBase >> 12;
    const int g = lane >> 2;
#pragma unroll
    for (int mi = 0; mi < 4; mi++) {
        const int r0 = rowBase + wm * 64 + mi * 16 + g;
#pragma unroll
        for (int ni = 0; ni < 4; ni++) {
            const int c0 = colBase + wn * 32 + ni * 8 + 2 * (lane & 3);
            const float kv0 = KV[b * 1024 + c0], kv1 = KV[b * 1024 + c0 + 1];
            const float ks0 = KS[b * 1024 + c0], ks1 = KS[b * 1024 + c0 + 1];
            const float bq0 = BQ[c0], bq1 = BQ[c0 + 1];
#pragma unroll
            for (int h = 0; h < 2; h++) {
                const int r = r0 + 8 * h;
                float Q0 = fmap(acc[mi][ni][2 * h + 0] + bq0);
                float Q1 = fmap(acc[mi][ni][2 * h + 1] + bq1);
                float a0 = __fdividef(Q0 * kv0, Q0 * ks0 + EPS);
                float a1 = __fdividef(Q1 * kv1, Q1 * ks1 + EPS);
                *(__half2*)(&ATT[(size_t)r * 1024 + c0]) = __floats2half2_rn(a0, a1);
            }
        }
    }
}

// ---------------- Kernel 3: output projection + gelu (fp32 out) ----------------
__global__ void __launch_bounds__(256) k_out(
    const __half* __restrict__ A, const __half* __restrict__ WT,
    const float* __restrict__ BO, float* __restrict__ OUT)
{
    GEMM_MAIN(WT)
    const int g = lane >> 2;
#pragma unroll
    for (int mi = 0; mi < 4; mi++) {
        const int r0 = rowBase + wm * 64 + mi * 16 + g;
#pragma unroll
        for (int ni = 0; ni < 4; ni++) {
            const int c0 = colBase + wn * 32 + ni * 8 + 2 * (lane & 3);
            const float bo0 = BO[c0], bo1 = BO[c0 + 1];
#pragma unroll
            for (int h = 0; h < 2; h++) {
                const int r = r0 + 8 * h;
                float o0 = gelu_t(acc[mi][ni][2 * h + 0] + bo0);
                float o1 = gelu_t(acc[mi][ni][2 * h + 1] + bo1);
                *(float2*)(&OUT[(size_t)r * 1024 + c0]) = make_float2(o0, o1);
            }
        }
    }
}

// ---------------- host launcher ----------------
extern "C" void kernel_launch(void* const* d_in, const int* in_sizes, int n_in,
                              void* d_out, int out_size)
{
    const float* x  = (const float*)d_in[0];
    const float* wq = (const float*)d_in[1];
    const float* bq = (const float*)d_in[2];
    const float* wk = (const float*)d_in[3];
    const float* bk = (const float*)d_in[4];
    const float* wv = (const float*)d_in[5];
    const float* bv = (const float*)d_in[6];
    const float* wo = (const float*)d_in[7];
    const float* bo = (const float*)d_in[8];
    float* out = (float*)d_out;

    void *p_xh, *p_wq, *p_wk, *p_wv, *p_wo, *p_att, *p_kv, *p_ks;
    cudaGetSymbolAddress(&p_xh,  g_xh);
    cudaGetSymbolAddress(&p_wq,  g_wqT);
    cudaGetSymbolAddress(&p_wk,  g_wkT);
    cudaGetSymbolAddress(&p_wv,  g_wvT);
    cudaGetSymbolAddress(&p_wo,  g_woT);
    cudaGetSymbolAddress(&p_att, g_att);
    cudaGetSymbolAddress(&p_kv,  g_KV);
    cudaGetSymbolAddress(&p_ks,  g_KS);

    const int SMB = 98304;   // 3 stages x 32K
    cudaFuncSetAttribute(k_kv,     cudaFuncAttributeMaxDynamicSharedMemorySize, SMB);
    cudaFuncSetAttribute(k_q_attn, cudaFuncAttributeMaxDynamicSharedMemorySize, SMB);
    cudaFuncSetAttribute(k_out,    cudaFuncAttributeMaxDynamicSharedMemorySize, SMB);

    // prep: x -> fp16; transpose+convert weights to [N,K] fp16; zero accumulators
    k_tohalf<<<32768, 256>>>((const float4*)x, (__half2*)p_xh, 8388608);
    k_wt<<<dim3(32, 32, 4), dim3(32, 8)>>>(wq, (__half*)p_wq, wk, (__half*)p_wk,
                                           wv, (__half*)p_wv, wo, (__half*)p_wo);
    k_zero<<<8, 1024>>>((float*)p_kv, (float*)p_ks, 8192);

    // 1) K,V projections + KV/Ksum reduction (K,V never materialized)
    k_kv<<<dim3(16, 256), 256, SMB>>>((const __half*)p_xh,
                                      (const __half*)p_wk, (const __half*)p_wv,
                                      bk, bv, (float*)p_kv, (float*)p_ks);
    // 2) Q projection + linear-attention epilogue -> attn scratch (fp16)
    k_q_attn<<<dim3(8, 256), 256, SMB>>>((const __half*)p_xh, (const __half*)p_wq, bq,
                                         (const float*)p_kv, (const float*)p_ks,
                                         (__half*)p_att);
    // 3) output projection + gelu
    k_out<<<dim3(8, 256), 256, SMB>>>((const __half*)p_att, (const __half*)p_wo, bo, out);
}